// round 6
// baseline (speedup 1.0000x reference)
#include <cuda_runtime.h>

#define NS   16
#define SS   32
#define ENCD 64
#define HIDD 128
#define OUTD 8
#define BMAX 32768
#define EPW  4

typedef unsigned long long u64;

__device__ float g_fin[BMAX * HIDD];   // 16 MB scratch (encoder -> gemm)

__device__ __forceinline__ u64 fma2(u64 a, u64 b, u64 c) {
    u64 d;
    asm("fma.rn.f32x2 %0, %1, %2, %3;" : "=l"(d) : "l"(a), "l"(b), "l"(c));
    return d;
}
__device__ __forceinline__ float lo_f(u64 v) { return __uint_as_float((unsigned)v); }
__device__ __forceinline__ float hi_f(u64 v) { return __uint_as_float((unsigned)(v >> 32)); }
__device__ __forceinline__ float sum2(u64 v) { return lo_f(v) + hi_f(v); }

// ======================= Kernel 1: encoder + masked mean =======================
__global__ __launch_bounds__(256)
void enc_kernel(const float* __restrict__ obs,
                const float* __restrict__ We, const float* __restrict__ be, int B)
{
    __shared__ float sWeP[16 * ENCD * 2];   // float2 pairs (We[2j][c], We[2j+1][c])

    const int tid  = threadIdx.x;
    const int lane = tid & 31;
    const int warp = tid >> 5;

    for (int i = tid; i < 16 * ENCD; i += 256) {
        int j = i >> 6, c = i & 63;
        ((float2*)sWeP)[i] = make_float2(We[2 * j * ENCD + c], We[(2 * j + 1) * ENCD + c]);
    }
    __syncthreads();

    // full encoder weight preload: 64 regs/lane
    const u64* sWeU = (const u64*)sWeP;
    u64 w0r[16], w1r[16];
#pragma unroll
    for (int j = 0; j < 16; j++) {
        w0r[j] = sWeU[j * 64 + lane];
        w1r[j] = sWeU[j * 64 + lane + 32];
    }
    const float be0 = __ldg(be + lane);
    const float be1 = __ldg(be + lane + 32);

    const int gw = blockIdx.x * 8 + warp;
    const int nw = gridDim.x * 8;

    for (int b = gw; b < B; b += nw) {
        const ulonglong2* rp = (const ulonglong2*)(obs + (size_t)b * (NS * SS));

        // ---- agent (n = 0)
        u64 a0 = 0, a1 = 0;
        {
            ulonglong2 rr[8];
#pragma unroll
            for (int i = 0; i < 8; i++) rr[i] = __ldg(rp + i);
#pragma unroll
            for (int i = 0; i < 8; i++) {
                a0 = fma2(w0r[2 * i],     rr[i].x, a0);
                a0 = fma2(w0r[2 * i + 1], rr[i].y, a0);
                a1 = fma2(w1r[2 * i],     rr[i].x, a1);
                a1 = fma2(w1r[2 * i + 1], rr[i].y, a1);
            }
        }
        const float g0 = fmaxf(sum2(a0) + be0, 0.f);
        const float g1 = fmaxf(sum2(a1) + be1, 0.f);

        // ---- neighbors: early-break on cumprod mask; flag-load pipelined one ahead
        float s0 = 0.f, s1 = 0.f, cnt = 0.f;
        ulonglong2 cur0 = __ldg(rp + 8);            // state 1, first 16B (carries flag)
#pragma unroll 1
        for (int n = 1; n < NS; n++) {
            if (lo_f(cur0.x) != 1.0f) break;        // warp-uniform
            cnt += 1.f;
            const ulonglong2* rn = rp + n * 8;
            ulonglong2 rr[7];
#pragma unroll
            for (int i = 0; i < 7; i++) rr[i] = __ldg(rn + 1 + i);
            ulonglong2 nxt0 = (n + 1 < NS) ? __ldg(rp + (n + 1) * 8) : make_ulonglong2(0, 0);

            u64 c0 = fma2(w0r[0], cur0.x, 0ull);
            c0 = fma2(w0r[1], cur0.y, c0);
            u64 c1 = fma2(w1r[0], cur0.x, 0ull);
            c1 = fma2(w1r[1], cur0.y, c1);
#pragma unroll
            for (int i = 0; i < 7; i++) {
                c0 = fma2(w0r[2 * i + 2], rr[i].x, c0);
                c0 = fma2(w0r[2 * i + 3], rr[i].y, c0);
                c1 = fma2(w1r[2 * i + 2], rr[i].x, c1);
                c1 = fma2(w1r[2 * i + 3], rr[i].y, c1);
            }
            s0 += fmaxf(sum2(c0) + be0, 0.f);
            s1 += fmaxf(sum2(c1) + be1, 0.f);
            cur0 = nxt0;
        }
        const float inv = 1.0f / fmaxf(cnt, 1.f);

        float* fo = g_fin + (size_t)b * HIDD;
        fo[lane]      = g0;
        fo[lane + 32] = g1;
        fo[lane + 64] = s0 * inv;
        fo[lane + 96] = s1 * inv;
    }
}

// ======================= Kernel 2: hidden GEMM + decode =======================
#define T2 512
#define W2 16
// smem floats: WfT4 16384 + WdT 1024 + bf 128 + bd 8 + per-warp fin EPW*128
#define SMEM2 (16384 + 1024 + 128 + 8 + W2 * (EPW * HIDD))

__global__ __launch_bounds__(T2, 2)
void gemm_kernel(const float* __restrict__ Wf, const float* __restrict__ bf,
                 const float* __restrict__ Wd, const float* __restrict__ bd,
                 float* __restrict__ out, int B)
{
    extern __shared__ float sm[];
    float* sWfT4 = sm;                 // 16384
    float* sWdT  = sWfT4 + 16384;      // 1024
    float* sbf   = sWdT + 1024;        // 128
    float* sbd   = sbf + 128;          // 8
    float* warpf = sbd + 8;

    const int tid  = threadIdx.x;
    const int lane = tid & 31;
    const int warp = tid >> 5;

    for (int i = tid; i < 32 * HIDD; i += T2) {
        int k2 = i >> 7, c = i & 127;
        const float* wp = Wf + (4 * k2) * HIDD + c;
        ((float4*)sWfT4)[i] = make_float4(wp[0], wp[HIDD], wp[2 * HIDD], wp[3 * HIDD]);
    }
    for (int i = tid; i < 64 * OUTD; i += T2) {
        int hp = i >> 3, o = i & 7;
        ((float2*)sWdT)[i] = make_float2(Wd[2 * hp * OUTD + o], Wd[(2 * hp + 1) * OUTD + o]);
    }
    if (tid < HIDD) sbf[tid] = bf[tid];
    if (tid < OUTD) sbd[tid] = bd[tid];
    __syncthreads();

    float* fin = warpf + warp * (EPW * HIDD);

    const int gw    = blockIdx.x * W2 + warp;
    const int nwarp = gridDim.x * W2;
    const int tasks = B / EPW;

    for (int t = gw; t < tasks; t += nwarp) {
        const int b0 = t * EPW;

        // ---- stage fin rows (coalesced 16B loads)
#pragma unroll
        for (int e = 0; e < EPW; e++) {
            const float4 v = __ldg((const float4*)(g_fin + (size_t)(b0 + e) * HIDD) + lane);
            ((float4*)(fin + e * HIDD))[lane] = v;
        }
        __syncwarp();

        // ---- hidden GEMM: EPW elements share W_f reads
        u64 acc[EPW][4];
#pragma unroll
        for (int e = 0; e < EPW; e++)
#pragma unroll
            for (int c = 0; c < 4; c++) acc[e][c] = 0ull;

        const ulonglong2* WT = (const ulonglong2*)sWfT4;
        const ulonglong2* fU = (const ulonglong2*)fin;
#pragma unroll 4
        for (int k2 = 0; k2 < 32; k2++) {
            const ulonglong2 w0 = WT[k2 * 128 + lane];
            const ulonglong2 w1 = WT[k2 * 128 + lane + 32];
            const ulonglong2 w2 = WT[k2 * 128 + lane + 64];
            const ulonglong2 w3 = WT[k2 * 128 + lane + 96];
#pragma unroll
            for (int e = 0; e < EPW; e++) {
                const ulonglong2 f = fU[e * 32 + k2];
                acc[e][0] = fma2(w0.x, f.x, acc[e][0]);
                acc[e][0] = fma2(w0.y, f.y, acc[e][0]);
                acc[e][1] = fma2(w1.x, f.x, acc[e][1]);
                acc[e][1] = fma2(w1.y, f.y, acc[e][1]);
                acc[e][2] = fma2(w2.x, f.x, acc[e][2]);
                acc[e][2] = fma2(w2.y, f.y, acc[e][2]);
                acc[e][3] = fma2(w3.x, f.x, acc[e][3]);
                acc[e][3] = fma2(w3.y, f.y, acc[e][3]);
            }
        }
        __syncwarp();   // fin reads done before hid overwrites

        // ---- epilogue + decode (hid overwrites fin[e])
        const int o = lane & 7, q = lane >> 3;
        const u64* wdU = (const u64*)sWdT;
#pragma unroll 1
        for (int e = 0; e < EPW; e++) {
            float* hid = fin + e * HIDD;
            hid[lane]      = fmaxf(sum2(acc[e][0]) + sbf[lane],      0.f);
            hid[lane + 32] = fmaxf(sum2(acc[e][1]) + sbf[lane + 32], 0.f);
            hid[lane + 64] = fmaxf(sum2(acc[e][2]) + sbf[lane + 64], 0.f);
            hid[lane + 96] = fmaxf(sum2(acc[e][3]) + sbf[lane + 96], 0.f);
            __syncwarp();

            const u64* hU = (const u64*)hid;
            u64 p = 0;
#pragma unroll
            for (int hp = 0; hp < 16; hp++)
                p = fma2(hU[q * 16 + hp], wdU[(q * 16 + hp) * OUTD + o], p);
            float ps = sum2(p);
            ps += __shfl_down_sync(0xffffffffu, ps, 16);
            ps += __shfl_down_sync(0xffffffffu, ps, 8);
            if (lane < 8) out[(size_t)(b0 + e) * OUTD + lane] = ps + sbd[lane];
            __syncwarp();
        }
    }
}

extern "C" void kernel_launch(void* const* d_in, const int* in_sizes, int n_in,
                              void* d_out, int out_size)
{
    const float* obs = (const float*)d_in[0];
    const float* We  = (const float*)d_in[1];
    const float* be  = (const float*)d_in[2];
    const float* Wf  = (const float*)d_in[3];
    const float* bf  = (const float*)d_in[4];
    const float* Wd  = (const float*)d_in[5];
    const float* bd  = (const float*)d_in[6];
    float* out = (float*)d_out;

    int B = in_sizes[0] / (NS * SS);
    if (B > BMAX) B = BMAX;

    const size_t smem2 = SMEM2 * sizeof(float);
    cudaFuncSetAttribute(gemm_kernel, cudaFuncAttributeMaxDynamicSharedMemorySize, (int)smem2);

    enc_kernel<<<296, 256>>>(obs, We, be, B);
    gemm_kernel<<<296, T2, smem2>>>(Wf, bf, Wd, bd, out, B);
}

// round 7
// speedup vs baseline: 1.3193x; 1.3193x over previous
#include <cuda_runtime.h>

#define NS   16
#define SS   32
#define ENCD 64
#define HIDD 128
#define OUTD 8
#define BMAX 32768
#define EPW  8     // elements per warp-PAIR in gemm

typedef unsigned long long u64;

__device__ float g_fin[BMAX * HIDD];   // 16 MB scratch (encoder -> gemm)

__device__ __forceinline__ u64 fma2(u64 a, u64 b, u64 c) {
    u64 d;
    asm("fma.rn.f32x2 %0, %1, %2, %3;" : "=l"(d) : "l"(a), "l"(b), "l"(c));
    return d;
}
__device__ __forceinline__ float lo_f(u64 v) { return __uint_as_float((unsigned)v); }
__device__ __forceinline__ float hi_f(u64 v) { return __uint_as_float((unsigned)(v >> 32)); }
__device__ __forceinline__ float sum2(u64 v) { return lo_f(v) + hi_f(v); }

// ======================= Kernel 1: encoder + masked mean =======================
// 128 threads/CTA, ~3 CTAs/SM. Ballot pre-scan gives the neighbor count up
// front; the state loop is software-pipelined (loads for n+1 issue before
// FMAs of n) with ping-pong buffers and no data-dependent branches.
__global__ __launch_bounds__(128)
void enc_kernel(const float* __restrict__ obs,
                const float* __restrict__ We, const float* __restrict__ be, int B)
{
    __shared__ float sWeP[16 * ENCD * 2];   // float2 (We[2j][c], We[2j+1][c])

    const int tid  = threadIdx.x;
    const int lane = tid & 31;
    const int warp = tid >> 5;

    for (int i = tid; i < 16 * ENCD; i += 128) {
        int j = i >> 6, c = i & 63;
        ((float2*)sWeP)[i] = make_float2(We[2 * j * ENCD + c], We[(2 * j + 1) * ENCD + c]);
    }
    __syncthreads();

    const u64* sWeU = (const u64*)sWeP;
    u64 w0r[16], w1r[16];
#pragma unroll
    for (int j = 0; j < 16; j++) {
        w0r[j] = sWeU[j * 64 + lane];
        w1r[j] = sWeU[j * 64 + lane + 32];
    }
    const float be0 = __ldg(be + lane);
    const float be1 = __ldg(be + lane + 32);

    const int gw = blockIdx.x * 4 + warp;
    const int nw = gridDim.x * 4;

    for (int b = gw; b < B; b += nw) {
        const float* base = obs + (size_t)b * (NS * SS);
        const ulonglong2* rp = (const ulonglong2*)base;

        // ---- flag pre-scan: lane n holds state n's flag; ballot -> count
        float fl = 1.0f;
        if (lane >= 1 && lane < NS) fl = __ldg(base + lane * SS);
        unsigned inval = __ballot_sync(0xffffffffu, fl != 1.0f) & 0xFFFEu;
        const int cnt = inval ? (__ffs(inval) - 2) : (NS - 1);   // valid neighbors

        // ---- pipelined loads: A = state0, Bb = state1 (always present)
        ulonglong2 A[8], Bb[8];
#pragma unroll
        for (int i = 0; i < 8; i++) A[i]  = __ldg(rp + i);
#pragma unroll
        for (int i = 0; i < 8; i++) Bb[i] = __ldg(rp + 8 + i);

        // ---- agent from A
        u64 a0 = 0, a1 = 0;
#pragma unroll
        for (int i = 0; i < 8; i++) {
            a0 = fma2(w0r[2 * i],     A[i].x, a0);
            a0 = fma2(w0r[2 * i + 1], A[i].y, a0);
            a1 = fma2(w1r[2 * i],     A[i].x, a1);
            a1 = fma2(w1r[2 * i + 1], A[i].y, a1);
        }
        const float g0 = fmaxf(sum2(a0) + be0, 0.f);
        const float g1 = fmaxf(sum2(a1) + be1, 0.f);

        // ---- neighbors: known trip count, ping-pong prefetch one state ahead
        float s0 = 0.f, s1 = 0.f;
        int n = 1;
        while (n <= cnt) {
            {   // consume Bb (state n), prefetch into A
                const int np = (n < cnt) ? n + 1 : cnt;
#pragma unroll
                for (int i = 0; i < 8; i++) A[i] = __ldg(rp + np * 8 + i);
                u64 c0 = 0, c1 = 0;
#pragma unroll
                for (int i = 0; i < 8; i++) {
                    c0 = fma2(w0r[2 * i],     Bb[i].x, c0);
                    c0 = fma2(w0r[2 * i + 1], Bb[i].y, c0);
                    c1 = fma2(w1r[2 * i],     Bb[i].x, c1);
                    c1 = fma2(w1r[2 * i + 1], Bb[i].y, c1);
                }
                s0 += fmaxf(sum2(c0) + be0, 0.f);
                s1 += fmaxf(sum2(c1) + be1, 0.f);
            }
            n++;
            if (n > cnt) break;
            {   // consume A (state n), prefetch into Bb
                const int np = (n < cnt) ? n + 1 : cnt;
#pragma unroll
                for (int i = 0; i < 8; i++) Bb[i] = __ldg(rp + np * 8 + i);
                u64 c0 = 0, c1 = 0;
#pragma unroll
                for (int i = 0; i < 8; i++) {
                    c0 = fma2(w0r[2 * i],     A[i].x, c0);
                    c0 = fma2(w0r[2 * i + 1], A[i].y, c0);
                    c1 = fma2(w1r[2 * i],     A[i].x, c1);
                    c1 = fma2(w1r[2 * i + 1], A[i].y, c1);
                }
                s0 += fmaxf(sum2(c0) + be0, 0.f);
                s1 += fmaxf(sum2(c1) + be1, 0.f);
            }
            n++;
        }
        const float inv = 1.0f / fmaxf((float)cnt, 1.f);

        float* fo = g_fin + (size_t)b * HIDD;
        fo[lane]      = g0;
        fo[lane + 32] = g1;
        fo[lane + 64] = s0 * inv;
        fo[lane + 96] = s1 * inv;
    }
}

// ======================= Kernel 2: hidden GEMM + decode =======================
// Warp-pairs: 2 warps share 8 elements; each warp owns 64 of the 128 output
// cols. Halves W_f shared traffic per element vs single-warp EPW=4 while
// keeping accumulators at 32 regs (fits 64-reg / 2-CTA budget).
#define T2 512
#define NPAIR 8
// smem floats: WfT4 16384 + WdT 1024 + bf 128 + bd 8 + per-pair fin/hid EPW*128
#define SMEM2 (16384 + 1024 + 128 + 8 + NPAIR * (EPW * HIDD))

__device__ __forceinline__ void pair_bar(int pairid) {
    asm volatile("bar.sync %0, %1;" :: "r"(pairid + 1), "r"(64) : "memory");
}

__global__ __launch_bounds__(T2, 2)
void gemm_kernel(const float* __restrict__ Wf, const float* __restrict__ bf,
                 const float* __restrict__ Wd, const float* __restrict__ bd,
                 float* __restrict__ out, int B)
{
    extern __shared__ float sm[];
    float* sWfT4 = sm;                 // 16384
    float* sWdT  = sWfT4 + 16384;      // 1024
    float* sbf   = sWdT + 1024;        // 128
    float* sbd   = sbf + 128;          // 8
    float* pairf = sbd + 8;

    const int tid  = threadIdx.x;
    const int lane = tid & 31;
    const int warp = tid >> 5;
    const int pair = warp >> 1;
    const int half = warp & 1;

    for (int i = tid; i < 32 * HIDD; i += T2) {
        int k2 = i >> 7, c = i & 127;
        const float* wp = Wf + (4 * k2) * HIDD + c;
        ((float4*)sWfT4)[i] = make_float4(wp[0], wp[HIDD], wp[2 * HIDD], wp[3 * HIDD]);
    }
    for (int i = tid; i < 64 * OUTD; i += T2) {
        int hp = i >> 3, o = i & 7;
        ((float2*)sWdT)[i] = make_float2(Wd[2 * hp * OUTD + o], Wd[(2 * hp + 1) * OUTD + o]);
    }
    if (tid < HIDD) sbf[tid] = bf[tid];
    if (tid < OUTD) sbd[tid] = bd[tid];
    __syncthreads();

    float* buf = pairf + pair * (EPW * HIDD);   // fin, later reused as hid
    const int cb = half * 64 + lane;            // this warp's low col

    const int gp    = blockIdx.x * NPAIR + pair;
    const int npair = gridDim.x * NPAIR;
    const int tasks = B / EPW;

    for (int t = gp; t < tasks; t += npair) {
        const int b0 = t * EPW;

        // ---- stage fin rows: each warp loads 4 of the 8 elements
#pragma unroll
        for (int j = 0; j < 4; j++) {
            const int e = half * 4 + j;
            const float4 v = __ldg((const float4*)(g_fin + (size_t)(b0 + e) * HIDD) + lane);
            ((float4*)(buf + e * HIDD))[lane] = v;
        }
        pair_bar(pair);

        // ---- hidden GEMM
        u64 acc[EPW][2];
#pragma unroll
        for (int e = 0; e < EPW; e++) { acc[e][0] = 0ull; acc[e][1] = 0ull; }

        const ulonglong2* WT = (const ulonglong2*)sWfT4;
        const ulonglong2* fU = (const ulonglong2*)buf;
#pragma unroll 2
        for (int k2 = 0; k2 < 32; k2++) {
            const ulonglong2 w0 = WT[k2 * 128 + cb];
            const ulonglong2 w1 = WT[k2 * 128 + cb + 32];
#pragma unroll
            for (int e = 0; e < EPW; e++) {
                const ulonglong2 f = fU[e * 32 + k2];
                acc[e][0] = fma2(w0.x, f.x, acc[e][0]);
                acc[e][0] = fma2(w0.y, f.y, acc[e][0]);
                acc[e][1] = fma2(w1.x, f.x, acc[e][1]);
                acc[e][1] = fma2(w1.y, f.y, acc[e][1]);
            }
        }
        pair_bar(pair);   // all fin reads done before hid overwrites

        // ---- epilogue: relu into buf (now hid)
        const float bfa = sbf[cb], bfb = sbf[cb + 32];
#pragma unroll
        for (int e = 0; e < EPW; e++) {
            buf[e * HIDD + cb]      = fmaxf(sum2(acc[e][0]) + bfa, 0.f);
            buf[e * HIDD + cb + 32] = fmaxf(sum2(acc[e][1]) + bfb, 0.f);
        }
        pair_bar(pair);

        // ---- decode: each warp handles 4 elements
        const int o = lane & 7, q = lane >> 3;
        const u64* wdU = (const u64*)sWdT;
#pragma unroll
        for (int j = 0; j < 4; j++) {
            const int e = half * 4 + j;
            const u64* hU = (const u64*)(buf + e * HIDD);
            u64 p = 0;
#pragma unroll
            for (int hp = 0; hp < 16; hp++)
                p = fma2(hU[q * 16 + hp], wdU[(q * 16 + hp) * OUTD + o], p);
            float ps = sum2(p);
            ps += __shfl_down_sync(0xffffffffu, ps, 16);
            ps += __shfl_down_sync(0xffffffffu, ps, 8);
            if (lane < 8) out[(size_t)(b0 + e) * OUTD + lane] = ps + sbd[lane];
        }
        pair_bar(pair);   // hid reads done before next task's fin staging
    }
}

extern "C" void kernel_launch(void* const* d_in, const int* in_sizes, int n_in,
                              void* d_out, int out_size)
{
    const float* obs = (const float*)d_in[0];
    const float* We  = (const float*)d_in[1];
    const float* be  = (const float*)d_in[2];
    const float* Wf  = (const float*)d_in[3];
    const float* bf  = (const float*)d_in[4];
    const float* Wd  = (const float*)d_in[5];
    const float* bd  = (const float*)d_in[6];
    float* out = (float*)d_out;

    int B = in_sizes[0] / (NS * SS);
    if (B > BMAX) B = BMAX;

    const size_t smem2 = SMEM2 * sizeof(float);
    cudaFuncSetAttribute(gemm_kernel, cudaFuncAttributeMaxDynamicSharedMemorySize, (int)smem2);

    enc_kernel<<<444, 128>>>(obs, We, be, B);
    gemm_kernel<<<296, T2, smem2>>>(Wf, bf, Wd, bd, out, B);
}